// round 6
// baseline (speedup 1.0000x reference)
#include <cuda_runtime.h>

typedef unsigned long long ull;

#define H      1024
#define NSTATE 32
#define NPAIR  16     // states packed 2-per-f32x2
#define LLEN   2048
#define CHUNK  16
#define TPB    128    // thread t owns l in [16t, 16t+16)

// ---- packed f32x2 helpers (sm_103a) ----
__device__ __forceinline__ ull f2_mul(ull a, ull b) {
    ull r; asm("mul.rn.f32x2 %0, %1, %2;" : "=l"(r) : "l"(a), "l"(b)); return r;
}
__device__ __forceinline__ ull f2_add(ull a, ull b) {
    ull r; asm("add.rn.f32x2 %0, %1, %2;" : "=l"(r) : "l"(a), "l"(b)); return r;
}
__device__ __forceinline__ ull f2_fma(ull a, ull b, ull c) {
    ull r; asm("fma.rn.f32x2 %0, %1, %2, %3;" : "=l"(r) : "l"(a), "l"(b), "l"(c)); return r;
}
__device__ __forceinline__ ull f2_neg(ull a) { return a ^ 0x8000000080000000ULL; }

__device__ __forceinline__ double2 csq(double2 a) {
    return make_double2(a.x * a.x - a.y * a.y, 2.0 * a.x * a.y);
}
__device__ __forceinline__ double2 cmul(double2 a, double2 b) {
    return make_double2(a.x * b.x - a.y * b.y, a.x * b.y + a.y * b.x);
}

__global__ void __launch_bounds__(TPB) s4d_kernel(
    const float* __restrict__ log_dt,
    const float* __restrict__ log_A_real,
    const float* __restrict__ A_imag,
    const float* __restrict__ B_re, const float* __restrict__ B_im,
    const float* __restrict__ C_re, const float* __restrict__ C_im,
    float* __restrict__ out)
{
    // packed-pair tables; each [..][4] row = (v_{2q}, v_{2q+1}, u_{2q}, u_{2q+1}) = 2 x f32x2
    __shared__ __align__(16) float TF[32][NPAIR][4];   // [lane][q]: (re, re, im, im) of A^(16*lane)  8KB
    __shared__ __align__(16) float WPF[4][NPAIR][4];   // [warp][q]: (wre, wre, wim, wim) of w*A^(512*warp)
    __shared__ __align__(16) float CC[NPAIR][4];       // (c1, c1, c2n, c2n): c1=2Re(Abar), c2n=-|Abar|^2
    __shared__ __align__(16) float AB[NPAIR][4];       // (are, are, -aim, -aim)
    __shared__ double2 sA16[NSTATE];                   // Abar^16 (fp64)
    __shared__ double2 sW[NSTATE];                     // w = C*B_bar (fp64)

    const int h    = blockIdx.x;
    const int tid  = threadIdx.x;
    const int warp = tid >> 5;
    const int lane = tid & 31;

    // ---- Phase A: per-state constants in fp64 (one warp) ----
    if (tid < NSTATE) {
        const int n   = tid;
        const int idx = h * NSTATE + n;
        double dt = exp((double)log_dt[h]);
        double Ar = -exp((double)log_A_real[idx]);
        double Ai = (double)A_imag[idx];
        double dr = dt * Ar, di = dt * Ai;
        double er  = exp(dr);
        double abr = er * cos(di), abi = er * sin(di);   // A_bar
        // B_bar = (A_bar - 1)/A * B ; w = C * B_bar
        double xr = abr - 1.0, xi = abi;
        double den = Ar * Ar + Ai * Ai;
        double qr = (xr * Ar + xi * Ai) / den;
        double qi = (xi * Ar - xr * Ai) / den;
        double Br = (double)B_re[idx], Bi = (double)B_im[idx];
        double bbr = qr * Br - qi * Bi, bbi = qr * Bi + qi * Br;
        double Cr = (double)C_re[idx], Ci = (double)C_im[idx];
        sW[n] = make_double2(Cr * bbr - Ci * bbi, Cr * bbi + Ci * bbr);

        const int q = n >> 1, o = n & 1;
        CC[q][o]     = (float)(2.0 * abr);
        CC[q][2 + o] = (float)(-(abr * abr + abi * abi));
        AB[q][o]     = (float)abr;
        AB[q][2 + o] = (float)(-abi);

        // A_bar^16 via 4 squarings
        double2 p = make_double2(abr, abi);
        #pragma unroll
        for (int k = 0; k < 4; k++) p = csq(p);
        sA16[n] = p;
    }
    __syncthreads();

    // ---- Phase B: fill T[lane] = A^(16*lane) and w' = w*A^(512*warp), all 128 threads ----
    {
        const int g = warp;          // 0..3: covers lanes [8g, 8g+8) and warp factor g
        const int n = lane;
        const int q = n >> 1, o = n & 1;
        double2 a16  = sA16[n];
        double2 a32  = csq(a16);
        double2 a64  = csq(a32);
        double2 a128 = csq(a64);
        double2 a256 = csq(a128);
        double2 a512 = csq(a256);
        double2 a1024 = csq(a512);

        // T entries for lanes t = 8g..8g+7: start at A^(128g)
        double2 p = make_double2(1.0, 0.0);
        if (g & 1) p = cmul(p, a128);
        if (g & 2) p = cmul(p, a256);
        #pragma unroll
        for (int j = 0; j < 8; j++) {
            TF[8 * g + j][q][o]     = (float)p.x;
            TF[8 * g + j][q][2 + o] = (float)p.y;
            p = cmul(p, a16);
        }

        // w'(warp g) = w * A^(512g)
        double2 v = sW[n];
        if (g & 1) v = cmul(v, a512);
        if (g & 2) v = cmul(v, a1024);
        WPF[g][q][o]     = (float)v.x;
        WPF[g][q][2 + o] = (float)v.y;
    }
    __syncthreads();

    // ---- Main: K[h, 16*tid + j] = sum_pairs x_j, x_j = Re(s * Abar^j), s = w'*T[lane] ----
    ull acc[CHUNK];
    #pragma unroll
    for (int j = 0; j < CHUNK; j++) acc[j] = 0ULL;

    for (int q = 0; q < NPAIR; q++) {
        const ulonglong2 W = *reinterpret_cast<const ulonglong2*>(&WPF[warp][q][0]); // x=wre, y=wim
        const ulonglong2 T = *reinterpret_cast<const ulonglong2*>(&TF[lane][q][0]);  // x=tre, y=tim
        const ulonglong2 C = *reinterpret_cast<const ulonglong2*>(&CC[q][0]);        // x=c1,  y=c2n
        const ulonglong2 A = *reinterpret_cast<const ulonglong2*>(&AB[q][0]);        // x=are, y=-aim

        // s = w' * T   (complex, packed over state pair)
        ull sre = f2_fma(W.x, T.x, f2_mul(f2_neg(W.y), T.y));
        ull sim = f2_fma(W.x, T.y, f2_mul(W.y, T.x));

        // x0 = Re(s); x1 = Re(s*Abar) = sre*are + sim*(-aim)
        ull x1 = f2_fma(sim, A.y, f2_mul(sre, A.x));
        acc[0] = f2_add(acc[0], sre);
        acc[1] = f2_add(acc[1], x1);

        // 2nd-order recurrence: x_{j+1} = c1*x_j + (c2n*x_{j-1})
        ull t = f2_mul(C.y, sre);
        #pragma unroll
        for (int j = 2; j < CHUNK; j++) {
            ull x2 = f2_fma(C.x, x1, t);
            t      = f2_mul(C.y, x1);
            acc[j] = f2_add(acc[j], x2);
            x1     = x2;
        }
    }

    // ---- Epilogue: fold pair halves, vector store ----
    float res[CHUNK];
    #pragma unroll
    for (int j = 0; j < CHUNK; j++) {
        float lo, hi;
        asm("mov.b64 {%0, %1}, %2;" : "=f"(lo), "=f"(hi) : "l"(acc[j]));
        res[j] = lo + hi;
    }
    float4* o4 = reinterpret_cast<float4*>(out + (size_t)h * LLEN + tid * CHUNK);
    #pragma unroll
    for (int j = 0; j < 4; j++)
        o4[j] = make_float4(res[4 * j], res[4 * j + 1], res[4 * j + 2], res[4 * j + 3]);
}

extern "C" void kernel_launch(void* const* d_in, const int* in_sizes, int n_in,
                              void* d_out, int out_size) {
    s4d_kernel<<<H, TPB>>>(
        (const float*)d_in[0],   // log_dt
        (const float*)d_in[1],   // log_A_real
        (const float*)d_in[2],   // A_imag
        (const float*)d_in[3],   // B_re
        (const float*)d_in[4],   // B_im
        (const float*)d_in[5],   // C_re
        (const float*)d_in[6],   // C_im
        (float*)d_out);
}